// round 14
// baseline (speedup 1.0000x reference)
#include <cuda_runtime.h>
#include <cuda_fp16.h>
#include <math.h>
#include <stdint.h>

// Problem constants
#define BMAX   16384
#define INDIM  128
#define STATE  64
#define HID    1024
#define NB     8
#define KACT   (INDIM + INDIM * NB)   // 1152
#define NOUT2  (8192 + 64)            // 8256
#define NOUT2P 8320                   // padded to multiple of 128

// ---------------- scratch ----------------
__device__ float  g_x   [BMAX * INDIM];
__device__ __half g_act [BMAX * KACT];            // [b][k]
__device__ __half g_kan [BMAX * HID];             // [b][h]
__device__ __half g_W1k [KACT * HID];             // [k][o]  k-row major
__device__ __half g_W2h [(size_t)HID * NOUT2P];   // [h][n]  k-row major
__device__ float  g_b2  [NOUT2];
__device__ int    g_cnt [BMAX / 128];             // per-row-panel producer count

// ---------------- helpers ----------------
__device__ __forceinline__ void ldsm4(uint32_t addr, uint32_t& r0, uint32_t& r1,
                                      uint32_t& r2, uint32_t& r3) {
    asm volatile("ldmatrix.sync.aligned.m8n8.x4.shared.b16 {%0,%1,%2,%3}, [%4];"
                 : "=r"(r0), "=r"(r1), "=r"(r2), "=r"(r3) : "r"(addr));
}
__device__ __forceinline__ void ldsm4t(uint32_t addr, uint32_t& r0, uint32_t& r1,
                                       uint32_t& r2, uint32_t& r3) {
    asm volatile("ldmatrix.sync.aligned.m8n8.x4.trans.shared.b16 {%0,%1,%2,%3}, [%4];"
                 : "=r"(r0), "=r"(r1), "=r"(r2), "=r"(r3) : "r"(addr));
}

__device__ __forceinline__ void mma_f16(float* d, const uint32_t* a, const uint32_t* b) {
    asm volatile(
        "mma.sync.aligned.m16n8k16.row.col.f32.f16.f16.f32 "
        "{%0,%1,%2,%3}, {%4,%5,%6,%7}, {%8,%9}, {%0,%1,%2,%3};"
        : "+f"(d[0]), "+f"(d[1]), "+f"(d[2]), "+f"(d[3])
        : "r"(a[0]), "r"(a[1]), "r"(a[2]), "r"(a[3]), "r"(b[0]), "r"(b[1]));
}

__device__ __forceinline__ void cpa16(uint32_t smem, const void* g) {
    asm volatile("cp.async.cg.shared.global [%0], [%1], 16;" :: "r"(smem), "l"(g));
}
__device__ __forceinline__ void cpa_commit() { asm volatile("cp.async.commit_group;"); }
__device__ __forceinline__ void cpa_wait1()  { asm volatile("cp.async.wait_group 1;"); }

__device__ __forceinline__ uint4 pack8h(const float* v) {
    __half2 h0 = __floats2half2_rn(v[0], v[1]);
    __half2 h1 = __floats2half2_rn(v[2], v[3]);
    __half2 h2 = __floats2half2_rn(v[4], v[5]);
    __half2 h3 = __floats2half2_rn(v[6], v[7]);
    return make_uint4(*(uint32_t*)&h0, *(uint32_t*)&h1, *(uint32_t*)&h2, *(uint32_t*)&h3);
}

// ---------------- K1a: build_act + W1k + b2 + counter reset ----------------
__device__ __forceinline__ float knot(int j) { return -1.0f + 0.4f * (float)(j - 3); }

#define NB_W1V ((KACT * HID / 8 + 255) / 256)     // 576
#define NB_B2V ((NOUT2 / 4 + 255) / 256)          // 9

__global__ __launch_bounds__(256) void k1a_prep(const float* __restrict__ state,
                                                const float* __restrict__ novelU,
                                                const float* __restrict__ scale_base,
                                                const float* __restrict__ scale_sp,
                                                const float* __restrict__ coef,
                                                const float* __restrict__ f_b,
                                                const float* __restrict__ bias_b,
                                                int nbAct, int B) {
    int bx = blockIdx.x, tid = threadIdx.x;
    if (bx < nbAct) {
        int idx = bx * 256 + tid;
        if (idx >= B * INDIM) return;
        int b = idx / INDIM, i = idx - b * INDIM;
        float x = (i < STATE) ? state[b * STATE + i] : novelU[b * (INDIM - STATE) + (i - STATE)];
        g_x[b * INDIM + i] = x;
        g_act[(size_t)b * KACT + i] = __float2half(__fdividef(x, 1.0f + __expf(-x)));
        float bb[11];
#pragma unroll
        for (int j = 0; j < 11; j++)
            bb[j] = (x >= knot(j) && x < knot(j + 1)) ? 1.0f : 0.0f;
#pragma unroll
        for (int ord = 1; ord <= 3; ord++) {
#pragma unroll
            for (int j = 0; j < 11 - 1; j++) {
                if (j >= 11 - ord) break;
                float l = (x - knot(j)) / (knot(j + ord) - knot(j));
                float r = (knot(j + ord + 1) - x) / (knot(j + ord + 1) - knot(j + 1));
                bb[j] = l * bb[j] + r * bb[j + 1];
            }
        }
        *(uint4*)&g_act[(size_t)b * KACT + INDIM + i * NB] = pack8h(bb);
    } else if (bx < nbAct + NB_W1V) {
        int idx8 = (bx - nbAct) * 256 + tid;
        if (idx8 >= KACT * HID / 8) return;
        int k = idx8 / (HID / 8), o8 = (idx8 % (HID / 8)) * 8;
        float v[8];
        if (k < INDIM) {
            float4 a = *(const float4*)(scale_base + k * HID + o8);
            float4 b = *(const float4*)(scale_base + k * HID + o8 + 4);
            v[0] = a.x; v[1] = a.y; v[2] = a.z; v[3] = a.w;
            v[4] = b.x; v[5] = b.y; v[6] = b.z; v[7] = b.w;
        } else {
            int kk = k - INDIM;
            int i = kk >> 3, c = kk & 7;
#pragma unroll
            for (int j = 0; j < 8; j++)
                v[j] = scale_sp[i * HID + o8 + j] * coef[((size_t)i * HID + o8 + j) * NB + c];
        }
        *(uint4*)&g_W1k[(size_t)k * HID + o8] = pack8h(v);
    } else if (bx < nbAct + NB_W1V + NB_B2V) {
        int idx4 = (bx - nbAct - NB_W1V) * 256 + tid;
        if (idx4 >= (NOUT2 + 3) / 4) return;
        int n4 = idx4 * 4;
        if (n4 + 3 < 8192) {
            *(float4*)&g_b2[n4] = *(const float4*)(f_b + n4);
        } else {
#pragma unroll
            for (int j = 0; j < 4; j++) {
                int n = n4 + j;
                if (n < NOUT2) g_b2[n] = (n < 8192) ? f_b[n] : bias_b[n - 8192];
            }
        }
    } else {
        if (tid < BMAX / 128) g_cnt[tid] = 0;   // reset producer counters
    }
}

// ---------------- K1w2: W2h convert (fork stream; gemm2-only dependency) ----
#define NB_W2V (((int)((size_t)HID * NOUT2P / 8) + 255) / 256)

__global__ __launch_bounds__(256) void k1w2_prep(const float* __restrict__ f_w,
                                                 const float* __restrict__ bias_w) {
    size_t idx8 = (size_t)blockIdx.x * 256 + threadIdx.x;
    if (idx8 >= (size_t)HID * NOUT2P / 8) return;
    int h = (int)(idx8 / (NOUT2P / 8)), n8 = (int)(idx8 % (NOUT2P / 8)) * 8;
    float v[8];
    if (n8 + 7 < 8192) {
        float4 a = *(const float4*)(f_w + (size_t)h * 8192 + n8);
        float4 b = *(const float4*)(f_w + (size_t)h * 8192 + n8 + 4);
        v[0] = a.x; v[1] = a.y; v[2] = a.z; v[3] = a.w;
        v[4] = b.x; v[5] = b.y; v[6] = b.z; v[7] = b.w;
    } else {
#pragma unroll
        for (int j = 0; j < 8; j++) {
            int n = n8 + j;
            v[j] = 0.0f;
            if (n < 8192)       v[j] = f_w[(size_t)h * 8192 + n];
            else if (n < NOUT2) v[j] = bias_w[h * 64 + (n - 8192)];
        }
    }
    *(uint4*)&g_W2h[(size_t)h * NOUT2P + n8] = pack8h(v);
}

// ---------------- FP16 tensor-core GEMM (trans-B, 2 CTAs/SM) ----------------
#define KC    64
#define SAH   72
#define SBN   136
#define A_ST  (128 * SAH * 2)
#define B_ST  (KC * SBN * 2)
#define STGB  (A_ST + B_ST)            // 35840
#define XSP   130

template<int K, int NBSTR, bool EPI2>
__device__ __forceinline__ void gemm_body(const __half* __restrict__ A,
                                          const __half* __restrict__ Bg,
                                          __half* __restrict__ C,
                                          float* __restrict__ outAB,
                                          float* __restrict__ outBias,
                                          float* __restrict__ outO,
                                          char* dynsmem, int row0, int col0) {
    uint32_t smem_addr = (uint32_t)__cvta_generic_to_shared(dynsmem);

    int tid = threadIdx.x;
    int lane = tid & 31, wid = tid >> 5;
    int m0w = (wid & 1) * 64;
    int n0w = (wid >> 1) * 32;

    int rowA  = lane & 15;
    int kAh   = 8 * (lane >> 4);
    int krowB = (lane & 7) + 8 * ((lane >> 3) & 1);
    int ncolB = 8 * (lane >> 4);

    float acc[4][4][4];
#pragma unroll
    for (int mt = 0; mt < 4; mt++)
#pragma unroll
        for (int nt = 0; nt < 4; nt++)
#pragma unroll
            for (int j = 0; j < 4; j++) acc[mt][nt][j] = 0.0f;

    const int nk = K / KC;

    auto load_stage = [&](int stg, int k0) {
        uint32_t base = smem_addr + stg * STGB;
#pragma unroll
        for (int c = 0; c < 8; c++) {
            if (c < 4) {
                int ch = tid + c * 256;
                int r = ch >> 3, off = (ch & 7) * 8;
                cpa16(base + (uint32_t)(r * SAH + off) * 2,
                      A + (size_t)(row0 + r) * K + k0 + off);
            } else {
                int ch = tid + (c - 4) * 256;
                int r = ch >> 4, off = (ch & 15) * 8;
                cpa16(base + A_ST + (uint32_t)(r * SBN + off) * 2,
                      Bg + (size_t)(k0 + r) * NBSTR + col0 + off);
            }
        }
    };

    load_stage(0, 0);
    cpa_commit();
    load_stage(1, KC);
    cpa_commit();

    for (int it = 0; it < nk; it++) {
        int cur = it % 3;
        cpa_wait1();
        __syncthreads();
        int nx = it + 2;
        if (nx < nk) load_stage(nx % 3, nx * KC);
        cpa_commit();

        uint32_t sA = smem_addr + cur * STGB;
        uint32_t sB = sA + A_ST;
#pragma unroll
        for (int ks = 0; ks < 4; ks++) {
            int kh = ks * 16;
            uint32_t a[4][4], b[2][4];
#pragma unroll
            for (int mt = 0; mt < 4; mt++) {
                uint32_t addr = sA + (uint32_t)((m0w + mt * 16 + rowA) * SAH + kh + kAh) * 2;
                ldsm4(addr, a[mt][0], a[mt][1], a[mt][2], a[mt][3]);
            }
#pragma unroll
            for (int ng = 0; ng < 2; ng++) {
                uint32_t addr = sB + (uint32_t)((kh + krowB) * SBN + n0w + ng * 16 + ncolB) * 2;
                ldsm4t(addr, b[ng][0], b[ng][1], b[ng][2], b[ng][3]);
            }
#pragma unroll
            for (int mt = 0; mt < 4; mt++)
#pragma unroll
                for (int nt = 0; nt < 4; nt++)
                    mma_f16(acc[mt][nt], a[mt], &b[nt >> 1][(nt & 1) * 2]);
        }
    }

    int gid = lane >> 2, tig = lane & 3;

#pragma unroll
    for (int mt = 0; mt < 4; mt++) {
#pragma unroll
        for (int nt = 0; nt < 4; nt++) {
            int r0r = row0 + m0w + mt * 16 + gid;
            int n   = col0 + n0w + nt * 8 + 2 * tig;
            if (!EPI2) {
                __half2 v01 = __floats2half2_rn(acc[mt][nt][0], acc[mt][nt][1]);
                __half2 v23 = __floats2half2_rn(acc[mt][nt][2], acc[mt][nt][3]);
                *(__half2*)(C + (size_t)r0r * HID + n)       = v01;
                *(__half2*)(C + (size_t)(r0r + 8) * HID + n) = v23;
            } else {
                if (n >= NOUT2) continue;
                float b0 = g_b2[n], b1 = g_b2[n + 1];
                float2 v01 = make_float2(acc[mt][nt][0] + b0, acc[mt][nt][1] + b1);
                float2 v23 = make_float2(acc[mt][nt][2] + b0, acc[mt][nt][3] + b1);
                if (n < 8192) {
                    *(float2*)(outAB + (size_t)r0r * 8192 + n)       = v01;
                    *(float2*)(outAB + (size_t)(r0r + 8) * 8192 + n) = v23;
                } else {
                    int nb = n - 8192;
                    *(float2*)(outBias + (size_t)r0r * 64 + nb)       = v01;
                    *(float2*)(outBias + (size_t)(r0r + 8) * 64 + nb) = v23;
                }
            }
        }
    }

    if (EPI2 && col0 < 8192) {
        float* xs  = (float*)dynsmem;
        float* red = xs + 128 * XSP;
        __syncthreads();
        for (int i = tid * 4; i < 128 * 128; i += 256 * 4) {
            int r = i >> 7, u = i & 127;
            float4 v = *(const float4*)(g_x + (size_t)(row0 + r) * INDIM + u);
            xs[r * XSP + u]     = v.x;
            xs[r * XSP + u + 1] = v.y;
            xs[r * XSP + u + 2] = v.z;
            xs[r * XSP + u + 3] = v.w;
        }
        __syncthreads();

        int nw = wid >> 1;
#pragma unroll
        for (int mt = 0; mt < 4; mt++) {
            int lr = m0w + mt * 16 + gid;
            float p0 = 0.0f, p1 = 0.0f;
#pragma unroll
            for (int nt = 0; nt < 4; nt++) {
                int u = n0w + nt * 8 + 2 * tig;
                float n_b0 = g_b2[col0 + u], n_b1 = g_b2[col0 + u + 1];
                float x00 = xs[lr * XSP + u],        x01 = xs[lr * XSP + u + 1];
                float x10 = xs[(lr + 8) * XSP + u],  x11 = xs[(lr + 8) * XSP + u + 1];
                p0 = fmaf(acc[mt][nt][0] + n_b0, x00, p0);
                p0 = fmaf(acc[mt][nt][1] + n_b1, x01, p0);
                p1 = fmaf(acc[mt][nt][2] + n_b0, x10, p1);
                p1 = fmaf(acc[mt][nt][3] + n_b1, x11, p1);
            }
            p0 += __shfl_xor_sync(0xffffffff, p0, 1);
            p0 += __shfl_xor_sync(0xffffffff, p0, 2);
            p1 += __shfl_xor_sync(0xffffffff, p1, 1);
            p1 += __shfl_xor_sync(0xffffffff, p1, 2);
            if (tig == 0) {
                red[nw * 128 + lr]     = p0;
                red[nw * 128 + lr + 8] = p1;
            }
        }
        __syncthreads();
        if (tid < 128) {
            float v = red[tid] + red[128 + tid] + red[256 + tid] + red[384 + tid];
            outO[(size_t)(row0 + tid) * 64 + (col0 >> 7)] = v;
        }
    }
}

// ---------------- fused gemm1 -> gemm2 with device-side row dependency ------
__global__ __launch_bounds__(256, 2) void mma_fused(float* __restrict__ outAB,
                                                    float* __restrict__ outBias,
                                                    float* __restrict__ outO,
                                                    int g1n) {
    extern __shared__ char dynsmem[];
    int bid = blockIdx.x;
    if (bid < g1n) {
        // gemm1 producer tile: row-major, 8 col tiles per row panel
        int row = bid >> 3, col = bid & 7;
        gemm_body<KACT, HID, false>(g_act, g_W1k, g_kan, nullptr, nullptr, nullptr,
                                    dynsmem, row * 128, col * 128);
        __threadfence();
        __syncthreads();
        if (threadIdx.x == 0) atomicAdd(&g_cnt[row], 1);
    } else {
        // gemm2 consumer tile: row-major, 65 col tiles per row panel
        int b2 = bid - g1n;
        int row = b2 / 65, col = b2 % 65;
        if (threadIdx.x == 0) {
            while (atomicAdd(&g_cnt[row], 0) < 8) __nanosleep(200);
        }
        __syncthreads();
        gemm_body<HID, NOUT2P, true>(g_kan, g_W2h, nullptr, outAB, outBias, outO,
                                     dynsmem, row * 128, col * 128);
    }
}

// ---------------- out += bias ----------------
__global__ void add_bias(const float* __restrict__ biasOut, float* __restrict__ outO, int n) {
    int i = blockIdx.x * blockDim.x + threadIdx.x;
    if (i < n) outO[i] += biasOut[i];
}

// ---------------- launch ----------------
extern "C" void kernel_launch(void* const* d_in, const int* in_sizes, int n_in,
                              void* d_out, int out_size) {
    const float* novelU     = (const float*)d_in[0];
    const float* state      = (const float*)d_in[1];
    const float* coef       = (const float*)d_in[2];
    const float* scale_base = (const float*)d_in[3];
    const float* scale_sp   = (const float*)d_in[4];
    const float* bias_w     = (const float*)d_in[5];
    const float* bias_b     = (const float*)d_in[6];
    const float* f_w        = (const float*)d_in[7];
    const float* f_b        = (const float*)d_in[8];
    float* out = (float*)d_out;

    int B = in_sizes[0] / 64;
    if (B > BMAX) B = BMAX;

    float* outO    = out;
    float* outAB   = out + (size_t)B * 64;
    float* outBias = out + (size_t)B * 64 + (size_t)B * 8192;

    const int smem_stage = 3 * STGB;
    const int smem_epi   = 128 * XSP * 4 + 4 * 128 * 4;
    const int smem_bytes = smem_epi > smem_stage ? smem_epi : smem_stage;

    static cudaStream_t s2 = nullptr;
    static cudaEvent_t evFork = nullptr, evJoin = nullptr;
    static bool init_done = false;
    if (!init_done) {
        cudaFuncSetAttribute(mma_fused,
                             cudaFuncAttributeMaxDynamicSharedMemorySize, smem_bytes);
        cudaStreamCreateWithFlags(&s2, cudaStreamNonBlocking);
        cudaEventCreateWithFlags(&evFork, cudaEventDisableTiming);
        cudaEventCreateWithFlags(&evJoin, cudaEventDisableTiming);
        init_done = true;
    }

    // fork: W2h convert concurrent with k1a (only the gemm2 half needs it)
    cudaEventRecord(evFork, 0);
    cudaStreamWaitEvent(s2, evFork, 0);
    k1w2_prep<<<NB_W2V, 256, 0, s2>>>(f_w, bias_w);
    cudaEventRecord(evJoin, s2);

    int nbAct = (B * INDIM + 255) / 256;
    k1a_prep<<<nbAct + NB_W1V + NB_B2V + 1, 256>>>(state, novelU, scale_base, scale_sp,
                                                   coef, f_b, bias_b, nbAct, B);

    cudaStreamWaitEvent(0, evJoin, 0);   // join before fused kernel (gemm2 part reads W2h)
    int rows = B / 128;
    int g1n = rows * 8;                   // gemm1 tiles
    int g2n = rows * 65;                  // gemm2 tiles (64 AB cols + 1 bias tile)
    mma_fused<<<g1n + g2n, 256, smem_bytes>>>(outAB, outBias, outO, g1n);

    add_bias<<<(B * 64 + 255) / 256, 256>>>(outBias, outO, B * 64);
}

// round 15
// speedup vs baseline: 1.0637x; 1.0637x over previous
#include <cuda_runtime.h>
#include <cuda_fp16.h>
#include <math.h>
#include <stdint.h>

// Problem constants
#define BMAX   16384
#define INDIM  128
#define STATE  64
#define HID    1024
#define NB     8
#define KACT   (INDIM + INDIM * NB)   // 1152
#define NOUT2  (8192 + 64)            // 8256
#define NOUT2P 8320                   // padded to multiple of 128

// ---------------- scratch ----------------
__device__ float  g_x   [BMAX * INDIM];
__device__ __half g_act [BMAX * KACT];            // [b][k]
__device__ __half g_kan [BMAX * HID];             // [b][h]
__device__ __half g_W1k [KACT * HID];             // [k][o]  k-row major
__device__ __half g_W2h [(size_t)HID * NOUT2P];   // [h][n]  k-row major
__device__ float  g_b2  [NOUT2];

// ---------------- helpers ----------------
__device__ __forceinline__ void ldsm4(uint32_t addr, uint32_t& r0, uint32_t& r1,
                                      uint32_t& r2, uint32_t& r3) {
    asm volatile("ldmatrix.sync.aligned.m8n8.x4.shared.b16 {%0,%1,%2,%3}, [%4];"
                 : "=r"(r0), "=r"(r1), "=r"(r2), "=r"(r3) : "r"(addr));
}
__device__ __forceinline__ void ldsm4t(uint32_t addr, uint32_t& r0, uint32_t& r1,
                                       uint32_t& r2, uint32_t& r3) {
    asm volatile("ldmatrix.sync.aligned.m8n8.x4.trans.shared.b16 {%0,%1,%2,%3}, [%4];"
                 : "=r"(r0), "=r"(r1), "=r"(r2), "=r"(r3) : "r"(addr));
}

__device__ __forceinline__ void mma_f16(float* d, const uint32_t* a, const uint32_t* b) {
    asm volatile(
        "mma.sync.aligned.m16n8k16.row.col.f32.f16.f16.f32 "
        "{%0,%1,%2,%3}, {%4,%5,%6,%7}, {%8,%9}, {%0,%1,%2,%3};"
        : "+f"(d[0]), "+f"(d[1]), "+f"(d[2]), "+f"(d[3])
        : "r"(a[0]), "r"(a[1]), "r"(a[2]), "r"(a[3]), "r"(b[0]), "r"(b[1]));
}

__device__ __forceinline__ void cpa16(uint32_t smem, const void* g) {
    asm volatile("cp.async.cg.shared.global [%0], [%1], 16;" :: "r"(smem), "l"(g));
}
__device__ __forceinline__ void cpa_commit() { asm volatile("cp.async.commit_group;"); }
__device__ __forceinline__ void cpa_wait1()  { asm volatile("cp.async.wait_group 1;"); }

__device__ __forceinline__ uint4 pack8h(const float* v) {
    __half2 h0 = __floats2half2_rn(v[0], v[1]);
    __half2 h1 = __floats2half2_rn(v[2], v[3]);
    __half2 h2 = __floats2half2_rn(v[4], v[5]);
    __half2 h3 = __floats2half2_rn(v[6], v[7]);
    return make_uint4(*(uint32_t*)&h0, *(uint32_t*)&h1, *(uint32_t*)&h2, *(uint32_t*)&h3);
}

// ---------------- K1a: build_act + W1k + b2 ----------------
#define NB_W1V ((KACT * HID / 8 + 255) / 256)     // 576
#define NB_B2V ((NOUT2 / 4 + 255) / 256)          // 9

__global__ __launch_bounds__(256) void k1a_prep(const float* __restrict__ state,
                                                const float* __restrict__ novelU,
                                                const float* __restrict__ scale_base,
                                                const float* __restrict__ scale_sp,
                                                const float* __restrict__ coef,
                                                const float* __restrict__ f_b,
                                                const float* __restrict__ bias_b,
                                                int nbAct, int B) {
    int bx = blockIdx.x, tid = threadIdx.x;
    if (bx < nbAct) {
        int idx = bx * 256 + tid;
        if (idx >= B * INDIM) return;
        int b = idx / INDIM, i = idx - b * INDIM;
        float x = (i < STATE) ? state[b * STATE + i] : novelU[b * (INDIM - STATE) + (i - STATE)];
        g_x[b * INDIM + i] = x;
        g_act[(size_t)b * KACT + i] = __float2half(__fdividef(x, 1.0f + __expf(-x)));
        // closed-form uniform cubic B-spline: only 4 bases nonzero per x
        float bb[8];
#pragma unroll
        for (int j = 0; j < 8; j++) bb[j] = 0.0f;
        float xi = (x + 2.2f) * 2.5f;       // knots at -2.2 + 0.4*j, j=0..11
        float fi = floorf(xi);
        int ii = (int)fi;
        if (ii >= 0 && ii <= 10) {
            float t  = xi - fi;              // local coord in [0,1)
            float omt = 1.0f - t;
            float t2 = t * t, t3 = t2 * t;
            float B0 = omt * omt * omt * (1.0f / 6.0f);
            float B1 = (3.0f * t3 - 6.0f * t2 + 4.0f) * (1.0f / 6.0f);
            float B2 = (-3.0f * t3 + 3.0f * t2 + 3.0f * t + 1.0f) * (1.0f / 6.0f);
            float B3 = t3 * (1.0f / 6.0f);
            int j0 = ii - 3;
            if (j0 >= 0 && j0 <= 7)         bb[j0]     = B0;
            if (j0 + 1 >= 0 && j0 + 1 <= 7) bb[j0 + 1] = B1;
            if (j0 + 2 >= 0 && j0 + 2 <= 7) bb[j0 + 2] = B2;
            if (j0 + 3 >= 0 && j0 + 3 <= 7) bb[j0 + 3] = B3;
        }
        *(uint4*)&g_act[(size_t)b * KACT + INDIM + i * NB] = pack8h(bb);
    } else if (bx < nbAct + NB_W1V) {
        int idx8 = (bx - nbAct) * 256 + tid;
        if (idx8 >= KACT * HID / 8) return;
        int k = idx8 / (HID / 8), o8 = (idx8 % (HID / 8)) * 8;
        float v[8];
        if (k < INDIM) {
            float4 a = *(const float4*)(scale_base + k * HID + o8);
            float4 b = *(const float4*)(scale_base + k * HID + o8 + 4);
            v[0] = a.x; v[1] = a.y; v[2] = a.z; v[3] = a.w;
            v[4] = b.x; v[5] = b.y; v[6] = b.z; v[7] = b.w;
        } else {
            int kk = k - INDIM;
            int i = kk >> 3, c = kk & 7;
#pragma unroll
            for (int j = 0; j < 8; j++)
                v[j] = scale_sp[i * HID + o8 + j] * coef[((size_t)i * HID + o8 + j) * NB + c];
        }
        *(uint4*)&g_W1k[(size_t)k * HID + o8] = pack8h(v);
    } else {
        int idx4 = (bx - nbAct - NB_W1V) * 256 + tid;
        if (idx4 >= (NOUT2 + 3) / 4) return;
        int n4 = idx4 * 4;
        if (n4 + 3 < 8192) {
            *(float4*)&g_b2[n4] = *(const float4*)(f_b + n4);
        } else {
#pragma unroll
            for (int j = 0; j < 4; j++) {
                int n = n4 + j;
                if (n < NOUT2) g_b2[n] = (n < 8192) ? f_b[n] : bias_b[n - 8192];
            }
        }
    }
}

// ---------------- K1w2: W2h convert (fork stream; gemm2-only dependency) ----
#define NB_W2V (((int)((size_t)HID * NOUT2P / 8) + 255) / 256)

__global__ __launch_bounds__(256) void k1w2_prep(const float* __restrict__ f_w,
                                                 const float* __restrict__ bias_w) {
    size_t idx8 = (size_t)blockIdx.x * 256 + threadIdx.x;
    if (idx8 >= (size_t)HID * NOUT2P / 8) return;
    int h = (int)(idx8 / (NOUT2P / 8)), n8 = (int)(idx8 % (NOUT2P / 8)) * 8;
    float v[8];
    if (n8 + 7 < 8192) {
        float4 a = *(const float4*)(f_w + (size_t)h * 8192 + n8);
        float4 b = *(const float4*)(f_w + (size_t)h * 8192 + n8 + 4);
        v[0] = a.x; v[1] = a.y; v[2] = a.z; v[3] = a.w;
        v[4] = b.x; v[5] = b.y; v[6] = b.z; v[7] = b.w;
    } else {
#pragma unroll
        for (int j = 0; j < 8; j++) {
            int n = n8 + j;
            v[j] = 0.0f;
            if (n < 8192)       v[j] = f_w[(size_t)h * 8192 + n];
            else if (n < NOUT2) v[j] = bias_w[h * 64 + (n - 8192)];
        }
    }
    *(uint4*)&g_W2h[(size_t)h * NOUT2P + n8] = pack8h(v);
}

// ---------------- FP16 tensor-core GEMM (trans-B, 2 CTAs/SM) ----------------
#define KC    64
#define SAH   72
#define SBN   136
#define A_ST  (128 * SAH * 2)
#define B_ST  (KC * SBN * 2)
#define STGB  (A_ST + B_ST)            // 35840
#define XSP   130

template<int K, int NBSTR, bool EPI2>
__device__ __forceinline__ void gemm_body(const __half* __restrict__ A,
                                          const __half* __restrict__ Bg,
                                          __half* __restrict__ C,
                                          float* __restrict__ outAB,
                                          float* __restrict__ outBias,
                                          float* __restrict__ outO,
                                          char* dynsmem, int row0, int col0) {
    uint32_t smem_addr = (uint32_t)__cvta_generic_to_shared(dynsmem);

    int tid = threadIdx.x;
    int lane = tid & 31, wid = tid >> 5;
    int m0w = (wid & 1) * 64;
    int n0w = (wid >> 1) * 32;

    int rowA  = lane & 15;
    int kAh   = 8 * (lane >> 4);
    int krowB = (lane & 7) + 8 * ((lane >> 3) & 1);
    int ncolB = 8 * (lane >> 4);

    float acc[4][4][4];
#pragma unroll
    for (int mt = 0; mt < 4; mt++)
#pragma unroll
        for (int nt = 0; nt < 4; nt++)
#pragma unroll
            for (int j = 0; j < 4; j++) acc[mt][nt][j] = 0.0f;

    const int nk = K / KC;

    auto load_stage = [&](int stg, int k0) {
        uint32_t base = smem_addr + stg * STGB;
#pragma unroll
        for (int c = 0; c < 8; c++) {
            if (c < 4) {
                int ch = tid + c * 256;
                int r = ch >> 3, off = (ch & 7) * 8;
                cpa16(base + (uint32_t)(r * SAH + off) * 2,
                      A + (size_t)(row0 + r) * K + k0 + off);
            } else {
                int ch = tid + (c - 4) * 256;
                int r = ch >> 4, off = (ch & 15) * 8;
                cpa16(base + A_ST + (uint32_t)(r * SBN + off) * 2,
                      Bg + (size_t)(k0 + r) * NBSTR + col0 + off);
            }
        }
    };

    load_stage(0, 0);
    cpa_commit();
    load_stage(1, KC);
    cpa_commit();

    for (int it = 0; it < nk; it++) {
        int cur = it % 3;
        cpa_wait1();
        __syncthreads();
        int nx = it + 2;
        if (nx < nk) load_stage(nx % 3, nx * KC);
        cpa_commit();

        uint32_t sA = smem_addr + cur * STGB;
        uint32_t sB = sA + A_ST;
#pragma unroll
        for (int ks = 0; ks < 4; ks++) {
            int kh = ks * 16;
            uint32_t a[4][4], b[2][4];
#pragma unroll
            for (int mt = 0; mt < 4; mt++) {
                uint32_t addr = sA + (uint32_t)((m0w + mt * 16 + rowA) * SAH + kh + kAh) * 2;
                ldsm4(addr, a[mt][0], a[mt][1], a[mt][2], a[mt][3]);
            }
#pragma unroll
            for (int ng = 0; ng < 2; ng++) {
                uint32_t addr = sB + (uint32_t)((kh + krowB) * SBN + n0w + ng * 16 + ncolB) * 2;
                ldsm4t(addr, b[ng][0], b[ng][1], b[ng][2], b[ng][3]);
            }
#pragma unroll
            for (int mt = 0; mt < 4; mt++)
#pragma unroll
                for (int nt = 0; nt < 4; nt++)
                    mma_f16(acc[mt][nt], a[mt], &b[nt >> 1][(nt & 1) * 2]);
        }
    }

    int gid = lane >> 2, tig = lane & 3;

#pragma unroll
    for (int mt = 0; mt < 4; mt++) {
#pragma unroll
        for (int nt = 0; nt < 4; nt++) {
            int r0r = row0 + m0w + mt * 16 + gid;
            int n   = col0 + n0w + nt * 8 + 2 * tig;
            if (!EPI2) {
                __half2 v01 = __floats2half2_rn(acc[mt][nt][0], acc[mt][nt][1]);
                __half2 v23 = __floats2half2_rn(acc[mt][nt][2], acc[mt][nt][3]);
                *(__half2*)(C + (size_t)r0r * HID + n)       = v01;
                *(__half2*)(C + (size_t)(r0r + 8) * HID + n) = v23;
            } else {
                if (n >= NOUT2) continue;
                float b0 = g_b2[n], b1 = g_b2[n + 1];
                float2 v01 = make_float2(acc[mt][nt][0] + b0, acc[mt][nt][1] + b1);
                float2 v23 = make_float2(acc[mt][nt][2] + b0, acc[mt][nt][3] + b1);
                if (n < 8192) {
                    *(float2*)(outAB + (size_t)r0r * 8192 + n)       = v01;
                    *(float2*)(outAB + (size_t)(r0r + 8) * 8192 + n) = v23;
                } else {
                    int nb = n - 8192;
                    *(float2*)(outBias + (size_t)r0r * 64 + nb)       = v01;
                    *(float2*)(outBias + (size_t)(r0r + 8) * 64 + nb) = v23;
                }
            }
        }
    }

    if (EPI2 && col0 < 8192) {
        float* xs  = (float*)dynsmem;
        float* red = xs + 128 * XSP;
        __syncthreads();
        for (int i = tid * 4; i < 128 * 128; i += 256 * 4) {
            int r = i >> 7, u = i & 127;
            float4 v = *(const float4*)(g_x + (size_t)(row0 + r) * INDIM + u);
            xs[r * XSP + u]     = v.x;
            xs[r * XSP + u + 1] = v.y;
            xs[r * XSP + u + 2] = v.z;
            xs[r * XSP + u + 3] = v.w;
        }
        __syncthreads();

        int nw = wid >> 1;
#pragma unroll
        for (int mt = 0; mt < 4; mt++) {
            int lr = m0w + mt * 16 + gid;
            float p0 = 0.0f, p1 = 0.0f;
#pragma unroll
            for (int nt = 0; nt < 4; nt++) {
                int u = n0w + nt * 8 + 2 * tig;
                float n_b0 = g_b2[col0 + u], n_b1 = g_b2[col0 + u + 1];
                float x00 = xs[lr * XSP + u],        x01 = xs[lr * XSP + u + 1];
                float x10 = xs[(lr + 8) * XSP + u],  x11 = xs[(lr + 8) * XSP + u + 1];
                p0 = fmaf(acc[mt][nt][0] + n_b0, x00, p0);
                p0 = fmaf(acc[mt][nt][1] + n_b1, x01, p0);
                p1 = fmaf(acc[mt][nt][2] + n_b0, x10, p1);
                p1 = fmaf(acc[mt][nt][3] + n_b1, x11, p1);
            }
            p0 += __shfl_xor_sync(0xffffffff, p0, 1);
            p0 += __shfl_xor_sync(0xffffffff, p0, 2);
            p1 += __shfl_xor_sync(0xffffffff, p1, 1);
            p1 += __shfl_xor_sync(0xffffffff, p1, 2);
            if (tig == 0) {
                red[nw * 128 + lr]     = p0;
                red[nw * 128 + lr + 8] = p1;
            }
        }
        __syncthreads();
        if (tid < 128) {
            float v = red[tid] + red[128 + tid] + red[256 + tid] + red[384 + tid];
            outO[(size_t)(row0 + tid) * 64 + (col0 >> 7)] = v;
        }
    }
}

__global__ __launch_bounds__(256, 2) void mma_gemm1() {
    extern __shared__ char dynsmem[];
    gemm_body<KACT, HID, false>(g_act, g_W1k, g_kan, nullptr, nullptr, nullptr,
                                dynsmem, blockIdx.y * 128, blockIdx.x * 128);
}

__global__ __launch_bounds__(256, 2) void mma_gemm2(float* __restrict__ outAB,
                                                    float* __restrict__ outBias,
                                                    float* __restrict__ outO) {
    extern __shared__ char dynsmem[];
    gemm_body<HID, NOUT2P, true>(g_kan, g_W2h, nullptr, outAB, outBias, outO,
                                 dynsmem, blockIdx.y * 128, blockIdx.x * 128);
}

// ---------------- out += bias (vectorized) ----------------
__global__ void add_bias(const float4* __restrict__ biasOut, float4* __restrict__ outO, int n4) {
    int i = blockIdx.x * blockDim.x + threadIdx.x;
    if (i < n4) {
        float4 a = outO[i], b = biasOut[i];
        a.x += b.x; a.y += b.y; a.z += b.z; a.w += b.w;
        outO[i] = a;
    }
}

// ---------------- launch ----------------
extern "C" void kernel_launch(void* const* d_in, const int* in_sizes, int n_in,
                              void* d_out, int out_size) {
    const float* novelU     = (const float*)d_in[0];
    const float* state      = (const float*)d_in[1];
    const float* coef       = (const float*)d_in[2];
    const float* scale_base = (const float*)d_in[3];
    const float* scale_sp   = (const float*)d_in[4];
    const float* bias_w     = (const float*)d_in[5];
    const float* bias_b     = (const float*)d_in[6];
    const float* f_w        = (const float*)d_in[7];
    const float* f_b        = (const float*)d_in[8];
    float* out = (float*)d_out;

    int B = in_sizes[0] / 64;
    if (B > BMAX) B = BMAX;

    float* outO    = out;
    float* outAB   = out + (size_t)B * 64;
    float* outBias = out + (size_t)B * 64 + (size_t)B * 8192;

    const int smem_stage = 3 * STGB;
    const int smem_epi   = 128 * XSP * 4 + 4 * 128 * 4;
    const int smem_bytes = smem_epi > smem_stage ? smem_epi : smem_stage;

    static cudaStream_t s2 = nullptr;
    static cudaEvent_t evFork = nullptr, evJoin = nullptr;
    static bool init_done = false;
    if (!init_done) {
        cudaFuncSetAttribute(mma_gemm1,
                             cudaFuncAttributeMaxDynamicSharedMemorySize, smem_bytes);
        cudaFuncSetAttribute(mma_gemm2,
                             cudaFuncAttributeMaxDynamicSharedMemorySize, smem_bytes);
        cudaStreamCreateWithFlags(&s2, cudaStreamNonBlocking);
        cudaEventCreateWithFlags(&evFork, cudaEventDisableTiming);
        cudaEventCreateWithFlags(&evJoin, cudaEventDisableTiming);
        init_done = true;
    }

    // fork: W2h convert runs concurrently with k1a + gemm1 (only gemm2 needs it)
    cudaEventRecord(evFork, 0);
    cudaStreamWaitEvent(s2, evFork, 0);
    k1w2_prep<<<NB_W2V, 256, 0, s2>>>(f_w, bias_w);
    cudaEventRecord(evJoin, s2);

    int nbAct = (B * INDIM + 255) / 256;
    k1a_prep<<<nbAct + NB_W1V + NB_B2V, 256>>>(state, novelU, scale_base, scale_sp,
                                               coef, f_b, bias_b, nbAct, B);

    dim3 g1(HID / 128, B / 128);
    mma_gemm1<<<g1, 256, smem_bytes>>>();

    cudaStreamWaitEvent(0, evJoin, 0);   // join before gemm2
    dim3 g2(NOUT2P / 128, B / 128);
    mma_gemm2<<<g2, 256, smem_bytes>>>(outAB, outBias, outO);

    add_bias<<<(B * 64 / 4 + 255) / 256, 256>>>((const float4*)outBias, (float4*)outO, B * 16);
}